// round 1
// baseline (speedup 1.0000x reference)
#include <cuda_runtime.h>
#include <cuda_bf16.h>
#include <cstdint>

// Embedding gather: out[r, :] = table[indices[r], :]
// n_rows = B*F = 819200, D = 64 floats (256 B per row).
// Layout: 16 threads per row, one float4 (16 B) per thread.
// Both the gather read and the output write are fully coalesced in
// 128B sectors; 16 lanes share one index (L1 broadcast).

static constexpr int D = 64;            // embedding dim (floats)
static constexpr int THREADS_PER_ROW = 16;  // D/4 float4 lanes

__global__ __launch_bounds__(256)
void gather_kernel(const int* __restrict__ indices,
                   const float* __restrict__ table,
                   float* __restrict__ out,
                   int n_rows)
{
    const long long gtid = (long long)blockIdx.x * blockDim.x + threadIdx.x;
    const long long row  = gtid >> 4;           // / THREADS_PER_ROW
    const int lane       = (int)(gtid & 15);    // % THREADS_PER_ROW
    if (row >= n_rows) return;

    const int idx = __ldg(indices + row);

    const float4* src = reinterpret_cast<const float4*>(table + (long long)idx * D) + lane;
    float4*       dst = reinterpret_cast<float4*>(out + row * D) + lane;
    *dst = __ldg(src);
}

extern "C" void kernel_launch(void* const* d_in, const int* in_sizes, int n_in,
                              void* d_out, int out_size)
{
    const int*   indices = (const int*)d_in[0];
    const float* table   = (const float*)d_in[1];
    float*       out     = (float*)d_out;

    const int n_rows = in_sizes[0];            // B*F = 819200
    const long long total_threads = (long long)n_rows * THREADS_PER_ROW;
    const int block = 256;
    const int grid  = (int)((total_threads + block - 1) / block);

    gather_kernel<<<grid, block>>>(indices, table, out, n_rows);
}

// round 2
// speedup vs baseline: 1.2584x; 1.2584x over previous
#include <cuda_runtime.h>
#include <cuda_bf16.h>
#include <cstdint>

// Embedding gather: out[r, :] = table[indices[r], :]
// n_rows = B*F = 819200, D = 64 floats (256 B per row).
//
// Layout: 16 threads per row (one float4 each). Each thread handles
// ROWS_PER_THREAD=4 rows with front-batched independent loads to get
// MLP=4 per thread (prior version had a serial idx->gather->store chain,
// MLP=1, DRAM stuck at 58%).
//
// Output is write-once: store with .cs (evict-first) so it doesn't
// displace table rows from L2.

static constexpr int D = 64;                // embedding dim (floats)
static constexpr int LANES = 16;            // D/4 float4 lanes per row
static constexpr int RPT = 4;               // rows per thread
static constexpr int BLOCK = 256;
static constexpr int ROWS_PER_BLOCK = (BLOCK / LANES) * RPT;  // 64

__global__ __launch_bounds__(BLOCK)
void gather_kernel(const int* __restrict__ indices,
                   const float* __restrict__ table,
                   float* __restrict__ out,
                   int n_rows)
{
    const int local_row = threadIdx.x >> 4;   // 0..15
    const int lane      = threadIdx.x & 15;   // 0..15
    const long long row_base = (long long)blockIdx.x * ROWS_PER_BLOCK + local_row;

    long long rows[RPT];
    int       idx[RPT];
    float4    vals[RPT];

    // Phase 1: batched independent index loads
#pragma unroll
    for (int k = 0; k < RPT; k++) {
        rows[k] = row_base + (long long)k * LANES;   // 16 rows per pass
        idx[k]  = (rows[k] < n_rows) ? __ldg(indices + rows[k]) : 0;
    }

    // Phase 2: batched independent table gathers (MLP = RPT)
#pragma unroll
    for (int k = 0; k < RPT; k++) {
        const float4* src =
            reinterpret_cast<const float4*>(table + (long long)idx[k] * D) + lane;
        vals[k] = __ldg(src);
    }

    // Phase 3: streaming stores (evict-first; output is write-once)
#pragma unroll
    for (int k = 0; k < RPT; k++) {
        if (rows[k] < n_rows) {
            float4* dst = reinterpret_cast<float4*>(out + rows[k] * D) + lane;
            __stcs(dst, vals[k]);
        }
    }
}

extern "C" void kernel_launch(void* const* d_in, const int* in_sizes, int n_in,
                              void* d_out, int out_size)
{
    const int*   indices = (const int*)d_in[0];
    const float* table   = (const float*)d_in[1];
    float*       out     = (float*)d_out;

    const int n_rows = in_sizes[0];            // B*F = 819200
    const int grid   = (n_rows + ROWS_PER_BLOCK - 1) / ROWS_PER_BLOCK;

    gather_kernel<<<grid, BLOCK>>>(indices, table, out, n_rows);
}